// round 10
// baseline (speedup 1.0000x reference)
#include <cuda_runtime.h>
#include <cuda_fp16.h>
#include <cstdint>

// ---------------------------------------------------------------------------
// MambaBlock: B=2, L=1024, Dm=1024, Di=2048, Nstate=64, Kconv=4
// v10: fp16 mma GEMMs (unchanged from v9);
//      scan = 8-way CHUNKED parallel scan (local scan + combine + correct).
// ---------------------------------------------------------------------------

#define BATCH 2
#define SEQ   1024
#define DM    1024
#define DI    2048
#define NST   64
#define KCONV 4
#define ROWS  (BATCH * SEQ)   // 2048
#define NCHUNK 8
#define CLEN   (SEQ / NCHUNK) // 128

__device__ float g_xr[ROWS * 2 * DI];
__device__ float g_xc[ROWS * DI];
__device__ float g_dt[ROWS * DI];
__device__ float g_B [ROWS * NST];
__device__ float g_yloc[ROWS * DI];                       // pass1 out
__device__ float g_hend [BATCH * DI * NCHUNK * NST];      // 8 MB
__device__ float g_pprod[BATCH * DI * NCHUNK * NST];      // 8 MB
__device__ float g_hinit[BATCH * DI * NCHUNK * NST];      // 8 MB

__device__ __half g_xn_h[ROWS * DM];
__device__ __half g_w1_h[2 * DI * DM];
__device__ __half g_xc_h[ROWS * DI];
__device__ __half g_dw_h[DI * DI];
__device__ __half g_z_h [ROWS * DI];
__device__ __half g_ow_h[DM * DI];

__device__ __forceinline__ float siluf(float x) { return x / (1.0f + __expf(-x)); }
__device__ __forceinline__ float softplusf(float x) {
    return fmaxf(x, 0.0f) + log1pf(__expf(-fabsf(x)));
}
__device__ __forceinline__ float ex2f(float x) {
    float r;
    asm("ex2.approx.f32 %0, %1;" : "=f"(r) : "f"(x));
    return r;
}

__device__ __forceinline__ uint32_t smem_u32(const void* p) {
    uint32_t r;
    asm("{ .reg .u64 t; cvta.to.shared.u64 t, %1; cvt.u32.u64 %0, t; }" : "=r"(r) : "l"(p));
    return r;
}

#define CP_ASYNC16(dst, src) \
    asm volatile("cp.async.cg.shared.global [%0], [%1], 16;" :: "r"(dst), "l"(src))
#define CP_COMMIT() asm volatile("cp.async.commit_group;" ::: "memory")
#define CP_WAIT1()  asm volatile("cp.async.wait_group 1;" ::: "memory")

#define LDSM4(r0, r1, r2, r3, a) \
    asm volatile("ldmatrix.sync.aligned.m8n8.x4.shared.b16 {%0,%1,%2,%3}, [%4];" \
        : "=r"(r0), "=r"(r1), "=r"(r2), "=r"(r3) : "r"(a))
#define LDSM2(r0, r1, a) \
    asm volatile("ldmatrix.sync.aligned.m8n8.x2.shared.b16 {%0,%1}, [%2];" \
        : "=r"(r0), "=r"(r1) : "r"(a))

#define MMA16816(d, a, b) \
    asm volatile("mma.sync.aligned.m16n8k16.row.col.f32.f16.f16.f32 " \
        "{%0,%1,%2,%3}, {%4,%5,%6,%7}, {%8,%9}, {%0,%1,%2,%3};" \
        : "+f"((d)[0]), "+f"((d)[1]), "+f"((d)[2]), "+f"((d)[3]) \
        : "r"((a)[0]), "r"((a)[1]), "r"((a)[2]), "r"((a)[3]), "r"((b)[0]), "r"((b)[1]))

// ============================ mma GEMM (unchanged from v9) =================
#define MM_BK    32
#define MM_PAD   40
#define MM_AARR  (128 * MM_PAD * 2)
#define MM_STAGE (2 * MM_AARR)
#define MM_SMEM  (3 * MM_STAGE)

template<int EPI>
__global__ __launch_bounds__(256, 2) void mma_gemm(
    const __half* __restrict__ A, const __half* __restrict__ B,
    float* __restrict__ C, int M, int N, int K,
    const float* __restrict__ bias, const float* __restrict__ add)
{
    extern __shared__ char smem[];
    const uint32_t sb = smem_u32(smem);
    const int tid  = threadIdx.x;
    const int wid  = tid >> 5;
    const int lane = tid & 31;
    const int wm   = wid >> 2;
    const int wn   = wid & 3;
    const int bm   = blockIdx.y * 128, bn = blockIdx.x * 128;

    const int lrow = tid >> 1;
    const int lcol = (tid & 1) * 16;
    const __half* gA = A + (size_t)(bm + lrow) * K + lcol;
    const __half* gB = B + (size_t)(bn + lrow) * K + lcol;
    const uint32_t ldst = (uint32_t)(lrow * MM_PAD + lcol) * 2;

    const int KT = K / MM_BK;
    const uint32_t a_off = (uint32_t)((wm * 64 + (lane & 15)) * MM_PAD + (lane >> 4) * 8) * 2;
    const uint32_t b_off = (uint32_t)((wn * 32 + (lane & 7)) * MM_PAD
                                      + ((lane >> 3) & 1) * 8) * 2;

    float acc[16][4];
    #pragma unroll
    for (int i = 0; i < 16; i++)
        #pragma unroll
        for (int j = 0; j < 4; j++) acc[i][j] = 0.0f;

    auto load_stage = [&](int st, int k0) {
        const uint32_t sa = sb + (uint32_t)st * MM_STAGE;
        CP_ASYNC16(sa + ldst,                 gA + k0);
        CP_ASYNC16(sa + ldst + 16,            gA + k0 + 8);
        CP_ASYNC16(sa + MM_AARR + ldst,       gB + k0);
        CP_ASYNC16(sa + MM_AARR + ldst + 16,  gB + k0 + 8);
    };

    load_stage(0, 0);     CP_COMMIT();
    load_stage(1, MM_BK); CP_COMMIT();

    int st = 0;
    for (int kt = 0; kt < KT; kt++) {
        CP_WAIT1();
        __syncthreads();
        const uint32_t stb = sb + (uint32_t)st * MM_STAGE;

        #pragma unroll
        for (int ks = 0; ks < 2; ks++) {
            const uint32_t kb = (uint32_t)(ks * 16) * 2;
            uint32_t ah[4][4], bh[4][2];
            #pragma unroll
            for (int mi = 0; mi < 4; mi++) {
                const uint32_t ao = stb + a_off + (uint32_t)(mi * 16 * MM_PAD) * 2 + kb;
                LDSM4(ah[mi][0], ah[mi][1], ah[mi][2], ah[mi][3], ao);
            }
            #pragma unroll
            for (int ni = 0; ni < 4; ni++) {
                const uint32_t bo = stb + MM_AARR + b_off
                                  + (uint32_t)(ni * 8 * MM_PAD) * 2 + kb;
                LDSM2(bh[ni][0], bh[ni][1], bo);
            }
            #pragma unroll
            for (int mi = 0; mi < 4; mi++)
                #pragma unroll
                for (int ni = 0; ni < 4; ni++)
                    MMA16816(acc[mi * 4 + ni], ah[mi], bh[ni]);
        }

        if (kt + 2 < KT) load_stage((st + 2) % 3, (kt + 2) * MM_BK);
        CP_COMMIT();
        st = (st + 1) % 3;
    }

    const int g  = lane >> 2;
    const int tc = (lane & 3) * 2;
    #pragma unroll
    for (int mi = 0; mi < 4; mi++) {
        #pragma unroll
        for (int ni = 0; ni < 4; ni++) {
            const float* a4 = acc[mi * 4 + ni];
            const int n = bn + wn * 32 + ni * 8 + tc;
            #pragma unroll
            for (int half_ = 0; half_ < 2; half_++) {
                const int m = bm + wm * 64 + mi * 16 + g + half_ * 8;
                float2 v = make_float2(a4[half_ * 2], a4[half_ * 2 + 1]);
                if (EPI == 1) {
                    v.x = softplusf(v.x + bias[n]);
                    v.y = softplusf(v.y + bias[n + 1]);
                } else if (EPI == 2) {
                    float2 s = *(const float2*)&add[(size_t)m * N + n];
                    v.x += s.x; v.y += s.y;
                }
                *(float2*)&C[(size_t)m * N + n] = v;
            }
        }
    }
}

// ============================ small kernels ================================

__global__ __launch_bounds__(256) void rmsnorm_kernel(
    const float* __restrict__ x, const float* __restrict__ w,
    __half* __restrict__ xh)
{
    int row = blockIdx.x, tid = threadIdx.x;
    const float* xr = x + (size_t)row * DM;
    float s = 0.0f;
    for (int i = tid; i < DM; i += 256) { float v = xr[i]; s += v * v; }
    #pragma unroll
    for (int o = 16; o > 0; o >>= 1) s += __shfl_down_sync(0xffffffffu, s, o);
    __shared__ float sm[8];
    if ((tid & 31) == 0) sm[tid >> 5] = s;
    __syncthreads();
    if (tid == 0) {
        float t = 0.0f;
        #pragma unroll
        for (int i = 0; i < 8; i++) t += sm[i];
        sm[0] = rsqrtf(t / (float)DM + 1e-6f);
    }
    __syncthreads();
    float inv = sm[0];
    for (int i = tid; i < DM; i += 256)
        xh[(size_t)row * DM + i] = __float2half(w[i] * xr[i] * inv);
}

__global__ __launch_bounds__(256) void cvt_f2h_kernel(
    const float* __restrict__ in, __half* __restrict__ out, int n4)
{
    int i = blockIdx.x * 256 + threadIdx.x;
    if (i >= n4) return;
    float4 v = *(const float4*)(in + (size_t)i * 4);
    __half2 p0 = __floats2half2_rn(v.x, v.y);
    __half2 p1 = __floats2half2_rn(v.z, v.w);
    *(uint2*)(out + (size_t)i * 4) = make_uint2(*(uint32_t*)&p0, *(uint32_t*)&p1);
}

__global__ __launch_bounds__(256) void conv_silu_kernel(
    const float* __restrict__ xr, const float* __restrict__ cw,
    const float* __restrict__ cb, float* __restrict__ xc,
    __half* __restrict__ xch)
{
    int idx = blockIdx.x * 256 + threadIdx.x;
    int c  = idx & (DI - 1);
    int bl = idx >> 11;
    int l  = bl & (SEQ - 1);
    int b  = bl >> 10;

    float acc = cb[c];
    #pragma unroll
    for (int k = 0; k < KCONV; k++) {
        int lp = l - (KCONV - 1) + k;
        if (lp >= 0)
            acc = fmaf(xr[((size_t)(b * SEQ + lp)) * (2 * DI) + c], cw[c * KCONV + k], acc);
    }
    float v = siluf(acc);
    xc[(size_t)bl * DI + c] = v;
    xch[(size_t)bl * DI + c] = __float2half(v);
}

#define GBM 128
#define GBK 16
#define SK_SLICES 16
#define SK_KLEN   (DI / SK_SLICES)

__global__ __launch_bounds__(256) void gemm_skinny64_splitk(
    const float* __restrict__ A, const float* __restrict__ B, float* __restrict__ C,
    int K)
{
    __shared__ float As[GBK][GBM + 4];
    __shared__ float Bs[GBK][64 + 4];

    const int tid = threadIdx.x;
    const int bm  = blockIdx.y * GBM;
    const int kb  = blockIdx.x * SK_KLEN;
    const int tx  = tid & 15;
    const int ty  = tid >> 4;
    const int lr  = tid >> 1;
    const int lc  = (tid & 1) * 8;
    const int lrB = tid >> 2;
    const int lcB = (tid & 3) * 4;

    const float* Aptr = A + (size_t)(bm + lr) * K + kb + lc;
    const float* Bptr = B + (size_t)lrB * K + kb + lcB;

    float acc[8][4];
    #pragma unroll
    for (int i = 0; i < 8; i++)
        #pragma unroll
        for (int j = 0; j < 4; j++) acc[i][j] = 0.0f;

    for (int k0 = 0; k0 < SK_KLEN; k0 += GBK) {
        float4 a0 = *(const float4*)(Aptr + k0);
        float4 a1 = *(const float4*)(Aptr + k0 + 4);
        float4 b0 = *(const float4*)(Bptr + k0);
        As[lc + 0][lr] = a0.x; As[lc + 1][lr] = a0.y;
        As[lc + 2][lr] = a0.z; As[lc + 3][lr] = a0.w;
        As[lc + 4][lr] = a1.x; As[lc + 5][lr] = a1.y;
        As[lc + 6][lr] = a1.z; As[lc + 7][lr] = a1.w;
        Bs[lcB + 0][lrB] = b0.x; Bs[lcB + 1][lrB] = b0.y;
        Bs[lcB + 2][lrB] = b0.z; Bs[lcB + 3][lrB] = b0.w;
        __syncthreads();
        #pragma unroll
        for (int k = 0; k < GBK; k++) {
            float4 av0 = *(const float4*)&As[k][ty * 8];
            float4 av1 = *(const float4*)&As[k][ty * 8 + 4];
            float4 bv0 = *(const float4*)&Bs[k][tx * 4];
            float av[8] = {av0.x, av0.y, av0.z, av0.w, av1.x, av1.y, av1.z, av1.w};
            float bv[4] = {bv0.x, bv0.y, bv0.z, bv0.w};
            #pragma unroll
            for (int i = 0; i < 8; i++)
                #pragma unroll
                for (int j = 0; j < 4; j++)
                    acc[i][j] = fmaf(av[i], bv[j], acc[i][j]);
        }
        __syncthreads();
    }
    #pragma unroll
    for (int i = 0; i < 8; i++) {
        int m = bm + ty * 8 + i;
        #pragma unroll
        for (int j = 0; j < 4; j++)
            atomicAdd(&C[(size_t)m * NST + tx * 4 + j], acc[i][j]);
    }
}

// ====================== chunked parallel scan ==============================
// warp w -> (b = w>>14, c = (w>>3)&2047, k = w&7); 2 states/lane.
// PASS 1: local scan over chunk k from h=0; emit yloc (= local y + D*x),
//         chunk-final h_end, and per-state decay product P.
__global__ __launch_bounds__(256) void scan_pass1(
    const float* __restrict__ xc, const float* __restrict__ dt,
    const float* __restrict__ Bs, const float* __restrict__ A_log,
    const float* __restrict__ Dp,
    float* __restrict__ yloc, float* __restrict__ hend, float* __restrict__ pprod)
{
    const int w    = blockIdx.x * 8 + (threadIdx.x >> 5);   // 0..32767
    const int lane = threadIdx.x & 31;
    const int k    = w & 7;
    const int c    = (w >> 3) & (DI - 1);
    const int b    = w >> 14;

    const float LOG2E = 1.4426950408889634f;
    const float a0 = -expf(A_log[c * NST + 2 * lane + 0]) * LOG2E;
    const float a1 = -expf(A_log[c * NST + 2 * lane + 1]) * LOG2E;
    const float Dc = Dp[c];

    const size_t row0 = (size_t)(b * SEQ + k * CLEN);
    const float* dt_p = dt + row0 * DI + c;
    const float* xc_p = xc + row0 * DI + c;
    const float* B_p  = Bs + row0 * NST + 2 * lane;
    float* yl_p = yloc + row0 * DI + c;

    float h0 = 0.f, h1 = 0.f, p0 = 1.f, p1 = 1.f;

    #pragma unroll 4
    for (int t = 0; t < CLEN; t++) {
        float dtv = dt_p[(size_t)t * DI];
        float xv  = xc_p[(size_t)t * DI];
        float2 Bv = *(const float2*)&B_p[(size_t)t * NST];
        float d0 = ex2f(a0 * dtv), d1 = ex2f(a1 * dtv);
        h0 = fmaf(d0, h0, Bv.x * xv);
        h1 = fmaf(d1, h1, Bv.y * xv);
        p0 *= d0; p1 *= d1;
        float y = h0 + h1;
        y += __shfl_down_sync(0xffffffffu, y, 16);
        y += __shfl_down_sync(0xffffffffu, y, 8);
        y += __shfl_down_sync(0xffffffffu, y, 4);
        y += __shfl_down_sync(0xffffffffu, y, 2);
        y += __shfl_down_sync(0xffffffffu, y, 1);
        if (lane == 0) yl_p[(size_t)t * DI] = y + Dc * xv;
    }

    const size_t idx = ((size_t)((b * DI + c) * NCHUNK + k)) * NST + 2 * lane;
    hend[idx] = h0;  hend[idx + 1] = h1;
    pprod[idx] = p0; pprod[idx + 1] = p1;
}

// PASS 2: per (b,c) serial combine across 8 chunks -> h_init per chunk.
__global__ __launch_bounds__(256) void scan_pass2(
    const float* __restrict__ hend, const float* __restrict__ pprod,
    float* __restrict__ hinit)
{
    const int w    = blockIdx.x * 8 + (threadIdx.x >> 5);   // 0..4095
    const int lane = threadIdx.x & 31;
    const int b    = w >> 11;
    const int c    = w & (DI - 1);

    const size_t base = ((size_t)(b * DI + c) * NCHUNK) * NST + 2 * lane;
    float hc0 = 0.f, hc1 = 0.f;
    #pragma unroll
    for (int k = 0; k < NCHUNK; k++) {
        const size_t i = base + (size_t)k * NST;
        hinit[i] = hc0; hinit[i + 1] = hc1;
        hc0 = fmaf(pprod[i],     hc0, hend[i]);
        hc1 = fmaf(pprod[i + 1], hc1, hend[i + 1]);
    }
}

// PASS 3: correction + gate. c_t = ad_t * c_{t-1} from c = h_init;
//         z = (yloc_t + sum_n c_t) * silu(res).
__global__ __launch_bounds__(256) void scan_pass3(
    const float* __restrict__ dt, const float* __restrict__ A_log,
    const float* __restrict__ yloc, const float* __restrict__ xr,
    const float* __restrict__ hinit, __half* __restrict__ zh)
{
    const int w    = blockIdx.x * 8 + (threadIdx.x >> 5);   // 0..32767
    const int lane = threadIdx.x & 31;
    const int k    = w & 7;
    const int c    = (w >> 3) & (DI - 1);
    const int b    = w >> 14;

    const float LOG2E = 1.4426950408889634f;
    const float a0 = -expf(A_log[c * NST + 2 * lane + 0]) * LOG2E;
    const float a1 = -expf(A_log[c * NST + 2 * lane + 1]) * LOG2E;

    const size_t idx = ((size_t)((b * DI + c) * NCHUNK + k)) * NST + 2 * lane;
    float c0 = hinit[idx], c1 = hinit[idx + 1];

    const size_t row0 = (size_t)(b * SEQ + k * CLEN);
    const float* dt_p = dt + row0 * DI + c;
    const float* yl_p = yloc + row0 * DI + c;
    const float* xr_p = xr + row0 * (2 * DI) + DI + c;
    __half* zh_p = zh + row0 * DI + c;

    #pragma unroll 4
    for (int t = 0; t < CLEN; t++) {
        float dtv = dt_p[(size_t)t * DI];
        c0 *= ex2f(a0 * dtv);
        c1 *= ex2f(a1 * dtv);
        float y = c0 + c1;
        y += __shfl_down_sync(0xffffffffu, y, 16);
        y += __shfl_down_sync(0xffffffffu, y, 8);
        y += __shfl_down_sync(0xffffffffu, y, 4);
        y += __shfl_down_sync(0xffffffffu, y, 2);
        y += __shfl_down_sync(0xffffffffu, y, 1);
        if (lane == 0) {
            float v   = yl_p[(size_t)t * DI] + y;
            float res = xr_p[(size_t)t * (2 * DI)];
            zh_p[(size_t)t * DI] = __float2half(v * siluf(res));
        }
    }
}

// ---------------------------------------------------------------------------
extern "C" void kernel_launch(void* const* d_in, const int* in_sizes, int n_in,
                              void* d_out, int out_size)
{
    const float* x        = (const float*)d_in[0];
    const float* norm_w   = (const float*)d_in[1];
    const float* in_proj  = (const float*)d_in[2];
    const float* conv_w   = (const float*)d_in[3];
    const float* conv_b   = (const float*)d_in[4];
    const float* x_proj   = (const float*)d_in[5];
    const float* dt_w     = (const float*)d_in[6];
    const float* dt_b     = (const float*)d_in[7];
    const float* A_log    = (const float*)d_in[8];
    const float* D_param  = (const float*)d_in[9];
    const float* out_proj = (const float*)d_in[10];
    float* out = (float*)d_out;

    float *xr, *xc, *dt, *Bssm, *yloc, *hend, *pprod, *hinit;
    __half *xnh, *w1h, *xch, *dwh, *zh, *owh;
    cudaGetSymbolAddress((void**)&xr,    g_xr);
    cudaGetSymbolAddress((void**)&xc,    g_xc);
    cudaGetSymbolAddress((void**)&dt,    g_dt);
    cudaGetSymbolAddress((void**)&Bssm,  g_B);
    cudaGetSymbolAddress((void**)&yloc,  g_yloc);
    cudaGetSymbolAddress((void**)&hend,  g_hend);
    cudaGetSymbolAddress((void**)&pprod, g_pprod);
    cudaGetSymbolAddress((void**)&hinit, g_hinit);
    cudaGetSymbolAddress((void**)&xnh,   g_xn_h);
    cudaGetSymbolAddress((void**)&w1h,   g_w1_h);
    cudaGetSymbolAddress((void**)&xch,   g_xc_h);
    cudaGetSymbolAddress((void**)&dwh,   g_dw_h);
    cudaGetSymbolAddress((void**)&zh,    g_z_h);
    cudaGetSymbolAddress((void**)&owh,   g_ow_h);

    cudaFuncSetAttribute((const void*)mma_gemm<0>,
                         cudaFuncAttributeMaxDynamicSharedMemorySize, MM_SMEM);
    cudaFuncSetAttribute((const void*)mma_gemm<1>,
                         cudaFuncAttributeMaxDynamicSharedMemorySize, MM_SMEM);
    cudaFuncSetAttribute((const void*)mma_gemm<2>,
                         cudaFuncAttributeMaxDynamicSharedMemorySize, MM_SMEM);

    cudaMemsetAsync(Bssm, 0, (size_t)ROWS * NST * sizeof(float), 0);

    cvt_f2h_kernel<<<(2*DI*DM/4 + 255)/256, 256>>>(in_proj, w1h, 2*DI*DM/4);
    rmsnorm_kernel<<<ROWS, 256>>>(x, norm_w, xnh);
    cvt_f2h_kernel<<<(DI*DI/4 + 255)/256, 256>>>(dt_w, dwh, DI*DI/4);

    // GEMM1: xr = xn @ in_proj^T   [2048 x 4096], K=1024
    mma_gemm<0><<<dim3(2*DI/128, ROWS/128), 256, MM_SMEM>>>(
        xnh, w1h, xr, ROWS, 2*DI, DM, nullptr, nullptr);

    conv_silu_kernel<<<ROWS * DI / 256, 256>>>(xr, conv_w, conv_b, xc, xch);

    // GEMM2: dt = softplus(xc @ dt_w^T + dt_b)   [2048 x 2048], K=2048
    mma_gemm<1><<<dim3(DI/128, ROWS/128), 256, MM_SMEM>>>(
        xch, dwh, dt, ROWS, DI, DI, dt_b, nullptr);

    cvt_f2h_kernel<<<(DM*DI/4 + 255)/256, 256>>>(out_proj, owh, DM*DI/4);

    gemm_skinny64_splitk<<<dim3(SK_SLICES, ROWS/GBM), 256>>>(
        xc, x_proj + (size_t)NST * DI, Bssm, DI);

    // chunked scan: 32768 warps (pass1/3), 4096 warps (pass2)
    scan_pass1<<<4096, 256>>>(xc, dt, Bssm, A_log, D_param, yloc, hend, pprod);
    scan_pass2<<<512, 256>>>(hend, pprod, hinit);
    scan_pass3<<<4096, 256>>>(dt, A_log, yloc, xr, hinit, zh);

    // GEMM3: out = z @ out_proj^T + x   [2048 x 1024], K=2048
    mma_gemm<2><<<dim3(DM/128, ROWS/128), 256, MM_SMEM>>>(
        zh, owh, out, ROWS, DM, DI, nullptr, x);
}

// round 11
// speedup vs baseline: 1.3976x; 1.3976x over previous
#include <cuda_runtime.h>
#include <cuda_fp16.h>
#include <cstdint>

// ---------------------------------------------------------------------------
// MambaBlock: B=2, L=1024, Dm=1024, Di=2048, Nstate=64, Kconv=4
// v11: fp16 mma GEMMs; scan = serial warp-per-channel with PACKED operands
//      (dt/xc/silu(res) in one float4, built for free in producer epilogues).
// ---------------------------------------------------------------------------

#define BATCH 2
#define SEQ   1024
#define DM    1024
#define DI    2048
#define NST   64
#define KCONV 4
#define ROWS  (BATCH * SEQ)   // 2048

__device__ float  g_xi[ROWS * DI];            // GEMM1 first-half output (conv in)
__device__ float  g_xc[ROWS * DI];            // conv out fp32 (skinny gemm in)
__device__ float4 g_pk[(ROWS + 1) * DI];      // {dt, xc, silu(res), pad}; +1 row pad
__device__ float  g_B [(ROWS + 1) * NST];     // +1 row pad for prefetch

__device__ __half g_xn_h[ROWS * DM];
__device__ __half g_w1_h[2 * DI * DM];
__device__ __half g_xc_h[ROWS * DI];
__device__ __half g_dw_h[DI * DI];
__device__ __half g_z_h [ROWS * DI];
__device__ __half g_ow_h[DM * DI];

__device__ __forceinline__ float siluf(float x) { return x / (1.0f + __expf(-x)); }
__device__ __forceinline__ float softplusf(float x) {
    return fmaxf(x, 0.0f) + log1pf(__expf(-fabsf(x)));
}
__device__ __forceinline__ float ex2f(float x) {
    float r;
    asm("ex2.approx.f32 %0, %1;" : "=f"(r) : "f"(x));
    return r;
}

__device__ __forceinline__ uint32_t smem_u32(const void* p) {
    uint32_t r;
    asm("{ .reg .u64 t; cvta.to.shared.u64 t, %1; cvt.u32.u64 %0, t; }" : "=r"(r) : "l"(p));
    return r;
}

#define CP_ASYNC16(dst, src) \
    asm volatile("cp.async.cg.shared.global [%0], [%1], 16;" :: "r"(dst), "l"(src))
#define CP_COMMIT() asm volatile("cp.async.commit_group;" ::: "memory")
#define CP_WAIT1()  asm volatile("cp.async.wait_group 1;" ::: "memory")

#define LDSM4(r0, r1, r2, r3, a) \
    asm volatile("ldmatrix.sync.aligned.m8n8.x4.shared.b16 {%0,%1,%2,%3}, [%4];" \
        : "=r"(r0), "=r"(r1), "=r"(r2), "=r"(r3) : "r"(a))
#define LDSM2(r0, r1, a) \
    asm volatile("ldmatrix.sync.aligned.m8n8.x2.shared.b16 {%0,%1}, [%2];" \
        : "=r"(r0), "=r"(r1) : "r"(a))

#define MMA16816(d, a, b) \
    asm volatile("mma.sync.aligned.m16n8k16.row.col.f32.f16.f16.f32 " \
        "{%0,%1,%2,%3}, {%4,%5,%6,%7}, {%8,%9}, {%0,%1,%2,%3};" \
        : "+f"((d)[0]), "+f"((d)[1]), "+f"((d)[2]), "+f"((d)[3]) \
        : "r"((a)[0]), "r"((a)[1]), "r"((a)[2]), "r"((a)[3]), "r"((b)[0]), "r"((b)[1]))

// ============================ mma GEMM =====================================
// C[m,n] = sum_k A[m,k]*B[n,k], fp16 operands, fp32 accum.
// Block 128x128, BK=32, 3-stage cp.async, 256 thr, 2 CTA/SM.
// EPI: 1 = dt GEMM: softplus(v+bias[n]) -> pk[m*DI+n].x
//      2 = out GEMM: v + add[m*N+n] -> C
//      3 = in_proj GEMM: n<DI -> C[m*DI+n] (xi); n>=DI -> silu(v) -> pk[...].z
#define MM_BK    32
#define MM_PAD   40
#define MM_AARR  (128 * MM_PAD * 2)
#define MM_STAGE (2 * MM_AARR)
#define MM_SMEM  (3 * MM_STAGE)

template<int EPI>
__global__ __launch_bounds__(256, 2) void mma_gemm(
    const __half* __restrict__ A, const __half* __restrict__ B,
    float* __restrict__ C, float* __restrict__ pkf,
    int M, int N, int K,
    const float* __restrict__ bias, const float* __restrict__ add)
{
    extern __shared__ char smem[];
    const uint32_t sb = smem_u32(smem);
    const int tid  = threadIdx.x;
    const int wid  = tid >> 5;
    const int lane = tid & 31;
    const int wm   = wid >> 2;
    const int wn   = wid & 3;
    const int bm   = blockIdx.y * 128, bn = blockIdx.x * 128;

    const int lrow = tid >> 1;
    const int lcol = (tid & 1) * 16;
    const __half* gA = A + (size_t)(bm + lrow) * K + lcol;
    const __half* gB = B + (size_t)(bn + lrow) * K + lcol;
    const uint32_t ldst = (uint32_t)(lrow * MM_PAD + lcol) * 2;

    const int KT = K / MM_BK;
    const uint32_t a_off = (uint32_t)((wm * 64 + (lane & 15)) * MM_PAD + (lane >> 4) * 8) * 2;
    const uint32_t b_off = (uint32_t)((wn * 32 + (lane & 7)) * MM_PAD
                                      + ((lane >> 3) & 1) * 8) * 2;

    float acc[16][4];
    #pragma unroll
    for (int i = 0; i < 16; i++)
        #pragma unroll
        for (int j = 0; j < 4; j++) acc[i][j] = 0.0f;

    auto load_stage = [&](int st, int k0) {
        const uint32_t sa = sb + (uint32_t)st * MM_STAGE;
        CP_ASYNC16(sa + ldst,                 gA + k0);
        CP_ASYNC16(sa + ldst + 16,            gA + k0 + 8);
        CP_ASYNC16(sa + MM_AARR + ldst,       gB + k0);
        CP_ASYNC16(sa + MM_AARR + ldst + 16,  gB + k0 + 8);
    };

    load_stage(0, 0);     CP_COMMIT();
    load_stage(1, MM_BK); CP_COMMIT();

    int st = 0;
    for (int kt = 0; kt < KT; kt++) {
        CP_WAIT1();
        __syncthreads();
        const uint32_t stb = sb + (uint32_t)st * MM_STAGE;

        #pragma unroll
        for (int ks = 0; ks < 2; ks++) {
            const uint32_t kb = (uint32_t)(ks * 16) * 2;
            uint32_t ah[4][4], bh[4][2];
            #pragma unroll
            for (int mi = 0; mi < 4; mi++) {
                const uint32_t ao = stb + a_off + (uint32_t)(mi * 16 * MM_PAD) * 2 + kb;
                LDSM4(ah[mi][0], ah[mi][1], ah[mi][2], ah[mi][3], ao);
            }
            #pragma unroll
            for (int ni = 0; ni < 4; ni++) {
                const uint32_t bo = stb + MM_AARR + b_off
                                  + (uint32_t)(ni * 8 * MM_PAD) * 2 + kb;
                LDSM2(bh[ni][0], bh[ni][1], bo);
            }
            #pragma unroll
            for (int mi = 0; mi < 4; mi++)
                #pragma unroll
                for (int ni = 0; ni < 4; ni++)
                    MMA16816(acc[mi * 4 + ni], ah[mi], bh[ni]);
        }

        if (kt + 2 < KT) load_stage((st + 2) % 3, (kt + 2) * MM_BK);
        CP_COMMIT();
        st = (st + 1) % 3;
    }

    const int g  = lane >> 2;
    const int tc = (lane & 3) * 2;
    #pragma unroll
    for (int mi = 0; mi < 4; mi++) {
        #pragma unroll
        for (int ni = 0; ni < 4; ni++) {
            const float* a4 = acc[mi * 4 + ni];
            const int n = bn + wn * 32 + ni * 8 + tc;
            #pragma unroll
            for (int half_ = 0; half_ < 2; half_++) {
                const int m = bm + wm * 64 + mi * 16 + g + half_ * 8;
                float2 v = make_float2(a4[half_ * 2], a4[half_ * 2 + 1]);
                if (EPI == 1) {
                    // dt -> pack slot 0 (stride-4 floats)
                    float* p = pkf + (size_t)(m * DI + n) * 4;
                    p[0] = softplusf(v.x + bias[n]);
                    p[4] = softplusf(v.y + bias[n + 1]);
                } else if (EPI == 2) {
                    float2 s = *(const float2*)&add[(size_t)m * N + n];
                    v.x += s.x; v.y += s.y;
                    *(float2*)&C[(size_t)m * N + n] = v;
                } else { // EPI == 3: in_proj split (whole block on one side of DI)
                    if (bn < DI) {
                        *(float2*)&C[(size_t)m * DI + n] = v;
                    } else {
                        float* p = pkf + (size_t)(m * DI + (n - DI)) * 4 + 2;
                        p[0] = siluf(v.x);
                        p[4] = siluf(v.y);
                    }
                }
            }
        }
    }
}

// ============================ small kernels ================================

__global__ __launch_bounds__(256) void rmsnorm_kernel(
    const float* __restrict__ x, const float* __restrict__ w,
    __half* __restrict__ xh)
{
    int row = blockIdx.x, tid = threadIdx.x;
    const float* xr = x + (size_t)row * DM;
    float s = 0.0f;
    for (int i = tid; i < DM; i += 256) { float v = xr[i]; s += v * v; }
    #pragma unroll
    for (int o = 16; o > 0; o >>= 1) s += __shfl_down_sync(0xffffffffu, s, o);
    __shared__ float sm[8];
    if ((tid & 31) == 0) sm[tid >> 5] = s;
    __syncthreads();
    if (tid == 0) {
        float t = 0.0f;
        #pragma unroll
        for (int i = 0; i < 8; i++) t += sm[i];
        sm[0] = rsqrtf(t / (float)DM + 1e-6f);
    }
    __syncthreads();
    float inv = sm[0];
    for (int i = tid; i < DM; i += 256)
        xh[(size_t)row * DM + i] = __float2half(w[i] * xr[i] * inv);
}

__global__ __launch_bounds__(256) void cvt_f2h_kernel(
    const float* __restrict__ in, __half* __restrict__ out, int n4)
{
    int i = blockIdx.x * 256 + threadIdx.x;
    if (i >= n4) return;
    float4 v = *(const float4*)(in + (size_t)i * 4);
    __half2 p0 = __floats2half2_rn(v.x, v.y);
    __half2 p1 = __floats2half2_rn(v.z, v.w);
    *(uint2*)(out + (size_t)i * 4) = make_uint2(*(uint32_t*)&p0, *(uint32_t*)&p1);
}

// causal depthwise conv + bias + SiLU; writes xc fp32, xc fp16, pack slot 1
__global__ __launch_bounds__(256) void conv_silu_kernel(
    const float* __restrict__ xi, const float* __restrict__ cw,
    const float* __restrict__ cb, float* __restrict__ xc,
    __half* __restrict__ xch, float* __restrict__ pkf)
{
    int idx = blockIdx.x * 256 + threadIdx.x;
    int c  = idx & (DI - 1);
    int bl = idx >> 11;
    int l  = bl & (SEQ - 1);
    int b  = bl >> 10;

    float acc = cb[c];
    #pragma unroll
    for (int k = 0; k < KCONV; k++) {
        int lp = l - (KCONV - 1) + k;
        if (lp >= 0)
            acc = fmaf(xi[((size_t)(b * SEQ + lp)) * DI + c], cw[c * KCONV + k], acc);
    }
    float v = siluf(acc);
    xc[(size_t)bl * DI + c]  = v;
    xch[(size_t)bl * DI + c] = __float2half(v);
    pkf[((size_t)bl * DI + c) * 4 + 1] = v;
}

#define GBM 128
#define GBK 16
#define SK_SLICES 16
#define SK_KLEN   (DI / SK_SLICES)

__global__ __launch_bounds__(256) void gemm_skinny64_splitk(
    const float* __restrict__ A, const float* __restrict__ B, float* __restrict__ C,
    int K)
{
    __shared__ float As[GBK][GBM + 4];
    __shared__ float Bs[GBK][64 + 4];

    const int tid = threadIdx.x;
    const int bm  = blockIdx.y * GBM;
    const int kb  = blockIdx.x * SK_KLEN;
    const int tx  = tid & 15;
    const int ty  = tid >> 4;
    const int lr  = tid >> 1;
    const int lc  = (tid & 1) * 8;
    const int lrB = tid >> 2;
    const int lcB = (tid & 3) * 4;

    const float* Aptr = A + (size_t)(bm + lr) * K + kb + lc;
    const float* Bptr = B + (size_t)lrB * K + kb + lcB;

    float acc[8][4];
    #pragma unroll
    for (int i = 0; i < 8; i++)
        #pragma unroll
        for (int j = 0; j < 4; j++) acc[i][j] = 0.0f;

    for (int k0 = 0; k0 < SK_KLEN; k0 += GBK) {
        float4 a0 = *(const float4*)(Aptr + k0);
        float4 a1 = *(const float4*)(Aptr + k0 + 4);
        float4 b0 = *(const float4*)(Bptr + k0);
        As[lc + 0][lr] = a0.x; As[lc + 1][lr] = a0.y;
        As[lc + 2][lr] = a0.z; As[lc + 3][lr] = a0.w;
        As[lc + 4][lr] = a1.x; As[lc + 5][lr] = a1.y;
        As[lc + 6][lr] = a1.z; As[lc + 7][lr] = a1.w;
        Bs[lcB + 0][lrB] = b0.x; Bs[lcB + 1][lrB] = b0.y;
        Bs[lcB + 2][lrB] = b0.z; Bs[lcB + 3][lrB] = b0.w;
        __syncthreads();
        #pragma unroll
        for (int k = 0; k < GBK; k++) {
            float4 av0 = *(const float4*)&As[k][ty * 8];
            float4 av1 = *(const float4*)&As[k][ty * 8 + 4];
            float4 bv0 = *(const float4*)&Bs[k][tx * 4];
            float av[8] = {av0.x, av0.y, av0.z, av0.w, av1.x, av1.y, av1.z, av1.w};
            float bv[4] = {bv0.x, bv0.y, bv0.z, bv0.w};
            #pragma unroll
            for (int i = 0; i < 8; i++)
                #pragma unroll
                for (int j = 0; j < 4; j++)
                    acc[i][j] = fmaf(av[i], bv[j], acc[i][j]);
        }
        __syncthreads();
    }
    #pragma unroll
    for (int i = 0; i < 8; i++) {
        int m = bm + ty * 8 + i;
        #pragma unroll
        for (int j = 0; j < 4; j++)
            atomicAdd(&C[(size_t)m * NST + tx * 4 + j], acc[i][j]);
    }
}

// ============================ scan =========================================
// Warp per (b,channel), 2 states/lane. Packed operand: ONE LDG.128 gives
// {dt, xc, silu(res)}; silu precomputed in GEMM1 epilogue. Prefetch dist 1
// (padded buffers, no bounds check). ~23 instr/step.
__global__ __launch_bounds__(256) void scan_kernel(
    const float4* __restrict__ pk, const float* __restrict__ Bs,
    const float* __restrict__ A_log, const float* __restrict__ Dp,
    __half* __restrict__ zh)
{
    const int w    = blockIdx.x * 8 + (threadIdx.x >> 5);   // 0..4095
    const int lane = threadIdx.x & 31;
    const int b    = w >> 11;
    const int c    = w & (DI - 1);

    const float LOG2E = 1.4426950408889634f;
    const float a0 = -expf(A_log[c * NST + 2 * lane + 0]) * LOG2E;
    const float a1 = -expf(A_log[c * NST + 2 * lane + 1]) * LOG2E;
    float h0 = 0.f, h1 = 0.f;
    const float Dc = Dp[c];

    const float4* p  = pk + (size_t)(b * SEQ) * DI + c;
    const float* B_p = Bs + (size_t)(b * SEQ) * NST + 2 * lane;
    __half* z_p = zh + (size_t)(b * SEQ) * DI + c;

    float4 cur = p[0];
    float2 Bv  = *(const float2*)B_p;

    #pragma unroll 2
    for (int l = 0; l < SEQ; l++) {
        // prefetch next step (padded rows make l+1 == SEQ safe)
        float4 nxt = p[(size_t)(l + 1) * DI];
        float2 nB  = *(const float2*)&B_p[(size_t)(l + 1) * NST];

        h0 = fmaf(ex2f(a0 * cur.x), h0, Bv.x * cur.y);
        h1 = fmaf(ex2f(a1 * cur.x), h1, Bv.y * cur.y);
        float y = h0 + h1;
        y += __shfl_down_sync(0xffffffffu, y, 16);
        y += __shfl_down_sync(0xffffffffu, y, 8);
        y += __shfl_down_sync(0xffffffffu, y, 4);
        y += __shfl_down_sync(0xffffffffu, y, 2);
        y += __shfl_down_sync(0xffffffffu, y, 1);
        if (lane == 0)
            z_p[(size_t)l * DI] = __float2half(fmaf(Dc, cur.y, y) * cur.z);

        cur = nxt; Bv = nB;
    }
}

// ---------------------------------------------------------------------------
extern "C" void kernel_launch(void* const* d_in, const int* in_sizes, int n_in,
                              void* d_out, int out_size)
{
    const float* x        = (const float*)d_in[0];
    const float* norm_w   = (const float*)d_in[1];
    const float* in_proj  = (const float*)d_in[2];
    const float* conv_w   = (const float*)d_in[3];
    const float* conv_b   = (const float*)d_in[4];
    const float* x_proj   = (const float*)d_in[5];
    const float* dt_w     = (const float*)d_in[6];
    const float* dt_b     = (const float*)d_in[7];
    const float* A_log    = (const float*)d_in[8];
    const float* D_param  = (const float*)d_in[9];
    const float* out_proj = (const float*)d_in[10];
    float* out = (float*)d_out;

    float *xi, *xc, *Bssm;
    float4* pk;
    __half *xnh, *w1h, *xch, *dwh, *zh, *owh;
    cudaGetSymbolAddress((void**)&xi,   g_xi);
    cudaGetSymbolAddress((void**)&xc,   g_xc);
    cudaGetSymbolAddress((void**)&pk,   g_pk);
    cudaGetSymbolAddress((void**)&Bssm, g_B);
    cudaGetSymbolAddress((void**)&xnh,  g_xn_h);
    cudaGetSymbolAddress((void**)&w1h,  g_w1_h);
    cudaGetSymbolAddress((void**)&xch,  g_xc_h);
    cudaGetSymbolAddress((void**)&dwh,  g_dw_h);
    cudaGetSymbolAddress((void**)&zh,   g_z_h);
    cudaGetSymbolAddress((void**)&owh,  g_ow_h);
    float* pkf = (float*)pk;

    cudaFuncSetAttribute((const void*)mma_gemm<1>,
                         cudaFuncAttributeMaxDynamicSharedMemorySize, MM_SMEM);
    cudaFuncSetAttribute((const void*)mma_gemm<2>,
                         cudaFuncAttributeMaxDynamicSharedMemorySize, MM_SMEM);
    cudaFuncSetAttribute((const void*)mma_gemm<3>,
                         cudaFuncAttributeMaxDynamicSharedMemorySize, MM_SMEM);

    cudaMemsetAsync(Bssm, 0, (size_t)ROWS * NST * sizeof(float), 0);

    cvt_f2h_kernel<<<(2*DI*DM/4 + 255)/256, 256>>>(in_proj, w1h, 2*DI*DM/4);
    rmsnorm_kernel<<<ROWS, 256>>>(x, norm_w, xnh);
    cvt_f2h_kernel<<<(DI*DI/4 + 255)/256, 256>>>(dt_w, dwh, DI*DI/4);

    // GEMM1 (EPI=3): n<DI -> xi; n>=DI -> silu -> pack slot 2
    mma_gemm<3><<<dim3(2*DI/128, ROWS/128), 256, MM_SMEM>>>(
        xnh, w1h, xi, pkf, ROWS, 2*DI, DM, nullptr, nullptr);

    // conv + silu -> xc fp32 + fp16 + pack slot 1
    conv_silu_kernel<<<ROWS * DI / 256, 256>>>(xi, conv_w, conv_b, xc, xch, pkf);

    // GEMM2 (EPI=1): dt = softplus(..) -> pack slot 0
    mma_gemm<1><<<dim3(DI/128, ROWS/128), 256, MM_SMEM>>>(
        xch, dwh, nullptr, pkf, ROWS, DI, DI, dt_b, nullptr);

    cvt_f2h_kernel<<<(DM*DI/4 + 255)/256, 256>>>(out_proj, owh, DM*DI/4);

    gemm_skinny64_splitk<<<dim3(SK_SLICES, ROWS/GBM), 256>>>(
        xc, x_proj + (size_t)NST * DI, Bssm, DI);

    // scan + gate -> z fp16 (4096 warps)
    scan_kernel<<<512, 256>>>(pk, Bssm, A_log, D_param, zh);

    // GEMM3 (EPI=2): out = z @ out_proj^T + x
    mma_gemm<2><<<dim3(DM/128, ROWS/128), 256, MM_SMEM>>>(
        zh, owh, out, nullptr, ROWS, DM, DI, nullptr, x);
}

// round 12
// speedup vs baseline: 1.7234x; 1.2331x over previous
#include <cuda_runtime.h>
#include <cuda_fp16.h>
#include <cstdint>

// ---------------------------------------------------------------------------
// MambaBlock: B=2, L=1024, Dm=1024, Di=2048, Nstate=64, Kconv=4
// v12: fp16 mma GEMMs (r11 config); scan = warp-per-channel with block-level
//      cp.async chunk staging of pk + B in smem (8 warps share B rows).
// ---------------------------------------------------------------------------

#define BATCH 2
#define SEQ   1024
#define DM    1024
#define DI    2048
#define NST   64
#define KCONV 4
#define ROWS  (BATCH * SEQ)   // 2048

__device__ float  g_xi[ROWS * DI];
__device__ float  g_xc[ROWS * DI];
__device__ float4 g_pk[(ROWS + 1) * DI];      // {dt, xc, silu(res), pad}
__device__ float  g_B [(ROWS + 1) * NST];

__device__ __half g_xn_h[ROWS * DM];
__device__ __half g_w1_h[2 * DI * DM];
__device__ __half g_xc_h[ROWS * DI];
__device__ __half g_dw_h[DI * DI];
__device__ __half g_z_h [ROWS * DI];
__device__ __half g_ow_h[DM * DI];

__device__ __forceinline__ float siluf(float x) { return x / (1.0f + __expf(-x)); }
__device__ __forceinline__ float softplusf(float x) {
    return fmaxf(x, 0.0f) + log1pf(__expf(-fabsf(x)));
}
__device__ __forceinline__ float ex2f(float x) {
    float r;
    asm("ex2.approx.f32 %0, %1;" : "=f"(r) : "f"(x));
    return r;
}

__device__ __forceinline__ uint32_t smem_u32(const void* p) {
    uint32_t r;
    asm("{ .reg .u64 t; cvta.to.shared.u64 t, %1; cvt.u32.u64 %0, t; }" : "=r"(r) : "l"(p));
    return r;
}

#define CP_ASYNC16(dst, src) \
    asm volatile("cp.async.cg.shared.global [%0], [%1], 16;" :: "r"(dst), "l"(src))
#define CP_COMMIT() asm volatile("cp.async.commit_group;" ::: "memory")
#define CP_WAIT1()  asm volatile("cp.async.wait_group 1;" ::: "memory")

#define LDSM4(r0, r1, r2, r3, a) \
    asm volatile("ldmatrix.sync.aligned.m8n8.x4.shared.b16 {%0,%1,%2,%3}, [%4];" \
        : "=r"(r0), "=r"(r1), "=r"(r2), "=r"(r3) : "r"(a))
#define LDSM2(r0, r1, a) \
    asm volatile("ldmatrix.sync.aligned.m8n8.x2.shared.b16 {%0,%1}, [%2];" \
        : "=r"(r0), "=r"(r1) : "r"(a))

#define MMA16816(d, a, b) \
    asm volatile("mma.sync.aligned.m16n8k16.row.col.f32.f16.f16.f32 " \
        "{%0,%1,%2,%3}, {%4,%5,%6,%7}, {%8,%9}, {%0,%1,%2,%3};" \
        : "+f"((d)[0]), "+f"((d)[1]), "+f"((d)[2]), "+f"((d)[3]) \
        : "r"((a)[0]), "r"((a)[1]), "r"((a)[2]), "r"((a)[3]), "r"((b)[0]), "r"((b)[1]))

// ============================ mma GEMM (r11 config) ========================
#define MM_BK    32
#define MM_PAD   40
#define MM_AARR  (128 * MM_PAD * 2)
#define MM_STAGE (2 * MM_AARR)
#define MM_SMEM  (3 * MM_STAGE)

template<int EPI>
__global__ __launch_bounds__(256, 2) void mma_gemm(
    const __half* __restrict__ A, const __half* __restrict__ B,
    float* __restrict__ C, float* __restrict__ pkf,
    int M, int N, int K,
    const float* __restrict__ bias, const float* __restrict__ add)
{
    extern __shared__ char smem[];
    const uint32_t sb = smem_u32(smem);
    const int tid  = threadIdx.x;
    const int wid  = tid >> 5;
    const int lane = tid & 31;
    const int wm   = wid >> 2;
    const int wn   = wid & 3;
    const int bm   = blockIdx.y * 128, bn = blockIdx.x * 128;

    const int lrow = tid >> 1;
    const int lcol = (tid & 1) * 16;
    const __half* gA = A + (size_t)(bm + lrow) * K + lcol;
    const __half* gB = B + (size_t)(bn + lrow) * K + lcol;
    const uint32_t ldst = (uint32_t)(lrow * MM_PAD + lcol) * 2;

    const int KT = K / MM_BK;
    const uint32_t a_off = (uint32_t)((wm * 64 + (lane & 15)) * MM_PAD + (lane >> 4) * 8) * 2;
    const uint32_t b_off = (uint32_t)((wn * 32 + (lane & 7)) * MM_PAD
                                      + ((lane >> 3) & 1) * 8) * 2;

    float acc[16][4];
    #pragma unroll
    for (int i = 0; i < 16; i++)
        #pragma unroll
        for (int j = 0; j < 4; j++) acc[i][j] = 0.0f;

    auto load_stage = [&](int st, int k0) {
        const uint32_t sa = sb + (uint32_t)st * MM_STAGE;
        CP_ASYNC16(sa + ldst,                 gA + k0);
        CP_ASYNC16(sa + ldst + 16,            gA + k0 + 8);
        CP_ASYNC16(sa + MM_AARR + ldst,       gB + k0);
        CP_ASYNC16(sa + MM_AARR + ldst + 16,  gB + k0 + 8);
    };

    load_stage(0, 0);     CP_COMMIT();
    load_stage(1, MM_BK); CP_COMMIT();

    int st = 0;
    for (int kt = 0; kt < KT; kt++) {
        CP_WAIT1();
        __syncthreads();
        const uint32_t stb = sb + (uint32_t)st * MM_STAGE;

        #pragma unroll
        for (int ks = 0; ks < 2; ks++) {
            const uint32_t kb = (uint32_t)(ks * 16) * 2;
            uint32_t ah[4][4], bh[4][2];
            #pragma unroll
            for (int mi = 0; mi < 4; mi++) {
                const uint32_t ao = stb + a_off + (uint32_t)(mi * 16 * MM_PAD) * 2 + kb;
                LDSM4(ah[mi][0], ah[mi][1], ah[mi][2], ah[mi][3], ao);
            }
            #pragma unroll
            for (int ni = 0; ni < 4; ni++) {
                const uint32_t bo = stb + MM_AARR + b_off
                                  + (uint32_t)(ni * 8 * MM_PAD) * 2 + kb;
                LDSM2(bh[ni][0], bh[ni][1], bo);
            }
            #pragma unroll
            for (int mi = 0; mi < 4; mi++)
                #pragma unroll
                for (int ni = 0; ni < 4; ni++)
                    MMA16816(acc[mi * 4 + ni], ah[mi], bh[ni]);
        }

        if (kt + 2 < KT) load_stage((st + 2) % 3, (kt + 2) * MM_BK);
        CP_COMMIT();
        st = (st + 1) % 3;
    }

    const int g  = lane >> 2;
    const int tc = (lane & 3) * 2;
    #pragma unroll
    for (int mi = 0; mi < 4; mi++) {
        #pragma unroll
        for (int ni = 0; ni < 4; ni++) {
            const float* a4 = acc[mi * 4 + ni];
            const int n = bn + wn * 32 + ni * 8 + tc;
            #pragma unroll
            for (int half_ = 0; half_ < 2; half_++) {
                const int m = bm + wm * 64 + mi * 16 + g + half_ * 8;
                float2 v = make_float2(a4[half_ * 2], a4[half_ * 2 + 1]);
                if (EPI == 1) {
                    float* p = pkf + (size_t)(m * DI + n) * 4;
                    p[0] = softplusf(v.x + bias[n]);
                    p[4] = softplusf(v.y + bias[n + 1]);
                } else if (EPI == 2) {
                    float2 s = *(const float2*)&add[(size_t)m * N + n];
                    v.x += s.x; v.y += s.y;
                    *(float2*)&C[(size_t)m * N + n] = v;
                } else { // EPI == 3
                    if (bn < DI) {
                        *(float2*)&C[(size_t)m * DI + n] = v;
                    } else {
                        float* p = pkf + (size_t)(m * DI + (n - DI)) * 4 + 2;
                        p[0] = siluf(v.x);
                        p[4] = siluf(v.y);
                    }
                }
            }
        }
    }
}

// ============================ small kernels ================================

__global__ __launch_bounds__(256) void rmsnorm_kernel(
    const float* __restrict__ x, const float* __restrict__ w,
    __half* __restrict__ xh)
{
    int row = blockIdx.x, tid = threadIdx.x;
    const float* xr = x + (size_t)row * DM;
    float s = 0.0f;
    for (int i = tid; i < DM; i += 256) { float v = xr[i]; s += v * v; }
    #pragma unroll
    for (int o = 16; o > 0; o >>= 1) s += __shfl_down_sync(0xffffffffu, s, o);
    __shared__ float sm[8];
    if ((tid & 31) == 0) sm[tid >> 5] = s;
    __syncthreads();
    if (tid == 0) {
        float t = 0.0f;
        #pragma unroll
        for (int i = 0; i < 8; i++) t += sm[i];
        sm[0] = rsqrtf(t / (float)DM + 1e-6f);
    }
    __syncthreads();
    float inv = sm[0];
    for (int i = tid; i < DM; i += 256)
        xh[(size_t)row * DM + i] = __float2half(w[i] * xr[i] * inv);
}

__global__ __launch_bounds__(256) void cvt_f2h_kernel(
    const float* __restrict__ in, __half* __restrict__ out, int n4)
{
    int i = blockIdx.x * 256 + threadIdx.x;
    if (i >= n4) return;
    float4 v = *(const float4*)(in + (size_t)i * 4);
    __half2 p0 = __floats2half2_rn(v.x, v.y);
    __half2 p1 = __floats2half2_rn(v.z, v.w);
    *(uint2*)(out + (size_t)i * 4) = make_uint2(*(uint32_t*)&p0, *(uint32_t*)&p1);
}

__global__ __launch_bounds__(256) void conv_silu_kernel(
    const float* __restrict__ xi, const float* __restrict__ cw,
    const float* __restrict__ cb, float* __restrict__ xc,
    __half* __restrict__ xch, float* __restrict__ pkf)
{
    int idx = blockIdx.x * 256 + threadIdx.x;
    int c  = idx & (DI - 1);
    int bl = idx >> 11;
    int l  = bl & (SEQ - 1);
    int b  = bl >> 10;

    float acc = cb[c];
    #pragma unroll
    for (int k = 0; k < KCONV; k++) {
        int lp = l - (KCONV - 1) + k;
        if (lp >= 0)
            acc = fmaf(xi[((size_t)(b * SEQ + lp)) * DI + c], cw[c * KCONV + k], acc);
    }
    float v = siluf(acc);
    xc[(size_t)bl * DI + c]  = v;
    xch[(size_t)bl * DI + c] = __float2half(v);
    pkf[((size_t)bl * DI + c) * 4 + 1] = v;
}

#define GBM 128
#define GBK 16
#define SK_SLICES 16
#define SK_KLEN   (DI / SK_SLICES)

__global__ __launch_bounds__(256) void gemm_skinny64_splitk(
    const float* __restrict__ A, const float* __restrict__ B, float* __restrict__ C,
    int K)
{
    __shared__ float As[GBK][GBM + 4];
    __shared__ float Bs[GBK][64 + 4];

    const int tid = threadIdx.x;
    const int bm  = blockIdx.y * GBM;
    const int kb  = blockIdx.x * SK_KLEN;
    const int tx  = tid & 15;
    const int ty  = tid >> 4;
    const int lr  = tid >> 1;
    const int lc  = (tid & 1) * 8;
    const int lrB = tid >> 2;
    const int lcB = (tid & 3) * 4;

    const float* Aptr = A + (size_t)(bm + lr) * K + kb + lc;
    const float* Bptr = B + (size_t)lrB * K + kb + lcB;

    float acc[8][4];
    #pragma unroll
    for (int i = 0; i < 8; i++)
        #pragma unroll
        for (int j = 0; j < 4; j++) acc[i][j] = 0.0f;

    for (int k0 = 0; k0 < SK_KLEN; k0 += GBK) {
        float4 a0 = *(const float4*)(Aptr + k0);
        float4 a1 = *(const float4*)(Aptr + k0 + 4);
        float4 b0 = *(const float4*)(Bptr + k0);
        As[lc + 0][lr] = a0.x; As[lc + 1][lr] = a0.y;
        As[lc + 2][lr] = a0.z; As[lc + 3][lr] = a0.w;
        As[lc + 4][lr] = a1.x; As[lc + 5][lr] = a1.y;
        As[lc + 6][lr] = a1.z; As[lc + 7][lr] = a1.w;
        Bs[lcB + 0][lrB] = b0.x; Bs[lcB + 1][lrB] = b0.y;
        Bs[lcB + 2][lrB] = b0.z; Bs[lcB + 3][lrB] = b0.w;
        __syncthreads();
        #pragma unroll
        for (int k = 0; k < GBK; k++) {
            float4 av0 = *(const float4*)&As[k][ty * 8];
            float4 av1 = *(const float4*)&As[k][ty * 8 + 4];
            float4 bv0 = *(const float4*)&Bs[k][tx * 4];
            float av[8] = {av0.x, av0.y, av0.z, av0.w, av1.x, av1.y, av1.z, av1.w};
            float bv[4] = {bv0.x, bv0.y, bv0.z, bv0.w};
            #pragma unroll
            for (int i = 0; i < 8; i++)
                #pragma unroll
                for (int j = 0; j < 4; j++)
                    acc[i][j] = fmaf(av[i], bv[j], acc[i][j]);
        }
        __syncthreads();
    }
    #pragma unroll
    for (int i = 0; i < 8; i++) {
        int m = bm + ty * 8 + i;
        #pragma unroll
        for (int j = 0; j < 4; j++)
            atomicAdd(&C[(size_t)m * NST + tx * 4 + j], acc[i][j]);
    }
}

// ============================ scan =========================================
// Block = 8 warps = 8 channels (same batch). Chunked cp.async staging:
// per 128-step chunk, stage B (32 KB, shared by all warps) and each warp's
// pk stream (16 KB) into smem, double buffered. Inner loop: pure LDS+compute.
#define SCH    8
#define SCHUNK 128
#define NCH    (SEQ / SCHUNK)            // 8 chunks
#define SC_BBUF   (SCHUNK * NST * 4)     // 32768 B
#define SC_PKBUF  (SCH * SCHUNK * 16)    // 16384 B
#define SC_STAGE  (SC_BBUF + SC_PKBUF)   // 49152 B
#define SC_SMEM   (2 * SC_STAGE)         // 98304 B

__global__ __launch_bounds__(256) void scan_kernel(
    const float4* __restrict__ pk, const float* __restrict__ Bs,
    const float* __restrict__ A_log, const float* __restrict__ Dp,
    __half* __restrict__ zh)
{
    extern __shared__ char smem[];
    const uint32_t sb = smem_u32(smem);
    const int tid  = threadIdx.x;
    const int wid  = tid >> 5;
    const int lane = tid & 31;
    const int b    = blockIdx.x >> 8;            // 0..1
    const int c0   = (blockIdx.x & 255) * SCH;   // channel base
    const int c    = c0 + wid;

    const float LOG2E = 1.4426950408889634f;
    const float a0 = -expf(A_log[c * NST + 2 * lane + 0]) * LOG2E;
    const float a1 = -expf(A_log[c * NST + 2 * lane + 1]) * LOG2E;
    float h0 = 0.f, h1 = 0.f;
    const float Dc = Dp[c];

    const float*  B_g  = Bs + (size_t)(b * SEQ) * NST;
    const float4* pk_g = pk + (size_t)(b * SEQ) * DI;
    __half* z_p = zh + (size_t)(b * SEQ) * DI + c;

    // block-wide chunk loader: B = 2048x16B, pk = 1024x16B
    auto load_chunk = [&](int st, int l0) {
        const uint32_t sB  = sb + (uint32_t)st * SC_STAGE;
        const uint32_t sPK = sB + SC_BBUF;
        #pragma unroll
        for (int r = 0; r < 8; r++) {
            const int i = tid + r * 256;             // 0..2047: s = i>>4, j = i&15
            const int s = i >> 4, j = i & 15;
            CP_ASYNC16(sB + (uint32_t)i * 16, &B_g[(size_t)(l0 + s) * NST + j * 4]);
        }
        #pragma unroll
        for (int r = 0; r < 4; r++) {
            const int i = tid + r * 256;             // 0..1023: ch = i>>7, s = i&127
            const int ch = i >> 7, s = i & 127;
            CP_ASYNC16(sPK + (uint32_t)i * 16, &pk_g[(size_t)(l0 + s) * DI + c0 + ch]);
        }
    };

    load_chunk(0, 0);      CP_COMMIT();
    load_chunk(1, SCHUNK); CP_COMMIT();

    for (int k = 0; k < NCH; k++) {
        CP_WAIT1();
        __syncthreads();
        const int st = k & 1;
        const uint32_t sB  = sb + (uint32_t)st * SC_STAGE;
        const uint32_t sPK = sB + SC_BBUF + (uint32_t)wid * (SCHUNK * 16);
        const int l0 = k * SCHUNK;

        #pragma unroll 4
        for (int s = 0; s < SCHUNK; s++) {
            float4 cur = *(const float4*)(smem + (sPK - sb) + s * 16);
            float2 Bv  = *(const float2*)(smem + (sB - sb) + s * (NST * 4) + lane * 8);
            h0 = fmaf(ex2f(a0 * cur.x), h0, Bv.x * cur.y);
            h1 = fmaf(ex2f(a1 * cur.x), h1, Bv.y * cur.y);
            float y = h0 + h1;
            y += __shfl_down_sync(0xffffffffu, y, 16);
            y += __shfl_down_sync(0xffffffffu, y, 8);
            y += __shfl_down_sync(0xffffffffu, y, 4);
            y += __shfl_down_sync(0xffffffffu, y, 2);
            y += __shfl_down_sync(0xffffffffu, y, 1);
            if (lane == 0)
                z_p[(size_t)(l0 + s) * DI] =
                    __float2half(fmaf(Dc, cur.y, y) * cur.z);
        }
        __syncthreads();   // all warps done with buffer st before refill

        if (k + 2 < NCH) load_chunk(st, (k + 2) * SCHUNK);
        CP_COMMIT();
    }
}

// ---------------------------------------------------------------------------
extern "C" void kernel_launch(void* const* d_in, const int* in_sizes, int n_in,
                              void* d_out, int out_size)
{
    const float* x        = (const float*)d_in[0];
    const float* norm_w   = (const float*)d_in[1];
    const float* in_proj  = (const float*)d_in[2];
    const float* conv_w   = (const float*)d_in[3];
    const float* conv_b   = (const float*)d_in[4];
    const float* x_proj   = (const float*)d_in[5];
    const float* dt_w     = (const float*)d_in[6];
    const float* dt_b     = (const float*)d_in[7];
    const float* A_log    = (const float*)d_in[8];
    const float* D_param  = (const float*)d_in[9];
    const float* out_proj = (const float*)d_in[10];
    float* out = (float*)d_out;

    float *xi, *xc, *Bssm;
    float4* pk;
    __half *xnh, *w1h, *xch, *dwh, *zh, *owh;
    cudaGetSymbolAddress((void**)&xi,   g_xi);
    cudaGetSymbolAddress((void**)&xc,   g_xc);
    cudaGetSymbolAddress((void**)&pk,   g_pk);
    cudaGetSymbolAddress((void**)&Bssm, g_B);
    cudaGetSymbolAddress((void**)&xnh,  g_xn_h);
    cudaGetSymbolAddress((void**)&w1h,  g_w1_h);
    cudaGetSymbolAddress((void**)&xch,  g_xc_h);
    cudaGetSymbolAddress((void**)&dwh,  g_dw_h);
    cudaGetSymbolAddress((void**)&zh,   g_z_h);
    cudaGetSymbolAddress((void**)&owh,  g_ow_h);
    float* pkf = (float*)pk;

    cudaFuncSetAttribute((const void*)mma_gemm<1>,
                         cudaFuncAttributeMaxDynamicSharedMemorySize, MM_SMEM);
    cudaFuncSetAttribute((const void*)mma_gemm<2>,
                         cudaFuncAttributeMaxDynamicSharedMemorySize, MM_SMEM);
    cudaFuncSetAttribute((const void*)mma_gemm<3>,
                         cudaFuncAttributeMaxDynamicSharedMemorySize, MM_SMEM);
    cudaFuncSetAttribute((const void*)scan_kernel,
                         cudaFuncAttributeMaxDynamicSharedMemorySize, SC_SMEM);

    cudaMemsetAsync(Bssm, 0, (size_t)ROWS * NST * sizeof(float), 0);

    cvt_f2h_kernel<<<(2*DI*DM/4 + 255)/256, 256>>>(in_proj, w1h, 2*DI*DM/4);
    rmsnorm_kernel<<<ROWS, 256>>>(x, norm_w, xnh);
    cvt_f2h_kernel<<<(DI*DI/4 + 255)/256, 256>>>(dt_w, dwh, DI*DI/4);

    // GEMM1 (EPI=3): n<DI -> xi; n>=DI -> silu -> pack slot 2
    mma_gemm<3><<<dim3(2*DI/128, ROWS/128), 256, MM_SMEM>>>(
        xnh, w1h, xi, pkf, ROWS, 2*DI, DM, nullptr, nullptr);

    conv_silu_kernel<<<ROWS * DI / 256, 256>>>(xi, conv_w, conv_b, xc, xch, pkf);

    // GEMM2 (EPI=1): dt = softplus(..) -> pack slot 0
    mma_gemm<1><<<dim3(DI/128, ROWS/128), 256, MM_SMEM>>>(
        xch, dwh, nullptr, pkf, ROWS, DI, DI, dt_b, nullptr);

    cvt_f2h_kernel<<<(DM*DI/4 + 255)/256, 256>>>(out_proj, owh, DM*DI/4);

    gemm_skinny64_splitk<<<dim3(SK_SLICES, ROWS/GBM), 256>>>(
        xc, x_proj + (size_t)NST * DI, Bssm, DI);

    // scan + gate -> z fp16 (512 blocks x 8 warps, smem-staged)
    scan_kernel<<<512, 256, SC_SMEM>>>(pk, Bssm, A_log, D_param, zh);

    // GEMM3 (EPI=2): out = z @ out_proj^T + x
    mma_gemm<2><<<dim3(DM/128, ROWS/128), 256, MM_SMEM>>>(
        zh, owh, out, nullptr, ROWS, DM, DI, nullptr, x);
}

// round 13
// speedup vs baseline: 1.8634x; 1.0812x over previous
#include <cuda_runtime.h>
#include <cuda_fp16.h>
#include <cstdint>

// ---------------------------------------------------------------------------
// MambaBlock: B=2, L=1024, Dm=1024, Di=2048, Nstate=64, Kconv=4
// v13: SoA epilogues (coalesced float2 GEMM stores), scan = 16 ch/block
//      single-wave smem-staged serial scan.
// ---------------------------------------------------------------------------

#define BATCH 2
#define SEQ   1024
#define DM    1024
#define DI    2048
#define NST   64
#define KCONV 4
#define ROWS  (BATCH * SEQ)   // 2048

__device__ float  g_xi  [ROWS * DI];          // GEMM1 first half (conv input)
__device__ float  g_sres[ROWS * DI];          // silu(res) from GEMM1
__device__ float  g_dt  [ROWS * DI];          // softplus dt from GEMM2
__device__ float  g_xc  [ROWS * DI];          // conv out fp32
__device__ float  g_B   [(ROWS + 1) * NST];

__device__ __half g_xn_h[ROWS * DM];
__device__ __half g_w1_h[2 * DI * DM];
__device__ __half g_xc_h[ROWS * DI];
__device__ __half g_dw_h[DI * DI];
__device__ __half g_z_h [ROWS * DI];
__device__ __half g_ow_h[DM * DI];

__device__ __forceinline__ float siluf(float x) { return x / (1.0f + __expf(-x)); }
__device__ __forceinline__ float softplusf(float x) {
    return fmaxf(x, 0.0f) + log1pf(__expf(-fabsf(x)));
}
__device__ __forceinline__ float ex2f(float x) {
    float r;
    asm("ex2.approx.f32 %0, %1;" : "=f"(r) : "f"(x));
    return r;
}

__device__ __forceinline__ uint32_t smem_u32(const void* p) {
    uint32_t r;
    asm("{ .reg .u64 t; cvta.to.shared.u64 t, %1; cvt.u32.u64 %0, t; }" : "=r"(r) : "l"(p));
    return r;
}

#define CP_ASYNC16(dst, src) \
    asm volatile("cp.async.cg.shared.global [%0], [%1], 16;" :: "r"(dst), "l"(src))
#define CP_COMMIT() asm volatile("cp.async.commit_group;" ::: "memory")
#define CP_WAIT1()  asm volatile("cp.async.wait_group 1;" ::: "memory")

#define LDSM4(r0, r1, r2, r3, a) \
    asm volatile("ldmatrix.sync.aligned.m8n8.x4.shared.b16 {%0,%1,%2,%3}, [%4];" \
        : "=r"(r0), "=r"(r1), "=r"(r2), "=r"(r3) : "r"(a))
#define LDSM2(r0, r1, a) \
    asm volatile("ldmatrix.sync.aligned.m8n8.x2.shared.b16 {%0,%1}, [%2];" \
        : "=r"(r0), "=r"(r1) : "r"(a))

#define MMA16816(d, a, b) \
    asm volatile("mma.sync.aligned.m16n8k16.row.col.f32.f16.f16.f32 " \
        "{%0,%1,%2,%3}, {%4,%5,%6,%7}, {%8,%9}, {%0,%1,%2,%3};" \
        : "+f"((d)[0]), "+f"((d)[1]), "+f"((d)[2]), "+f"((d)[3]) \
        : "r"((a)[0]), "r"((a)[1]), "r"((a)[2]), "r"((a)[3]), "r"((b)[0]), "r"((b)[1]))

// ============================ mma GEMM =====================================
// EPI: 1 = C[m*N+n] = softplus(v + bias[n])             (dt GEMM)
//      2 = C[m*N+n] = v + add[m*N+n]                     (out GEMM)
//      3 = bn<DI: C[m*DI+n] = v (xi); else D2[m*DI+n-DI] = silu(v)
#define MM_BK    32
#define MM_PAD   40
#define MM_AARR  (128 * MM_PAD * 2)
#define MM_STAGE (2 * MM_AARR)
#define MM_SMEM  (3 * MM_STAGE)

template<int EPI>
__global__ __launch_bounds__(256, 2) void mma_gemm(
    const __half* __restrict__ A, const __half* __restrict__ B,
    float* __restrict__ C, float* __restrict__ D2,
    int M, int N, int K,
    const float* __restrict__ bias, const float* __restrict__ add)
{
    extern __shared__ char smem[];
    const uint32_t sb = smem_u32(smem);
    const int tid  = threadIdx.x;
    const int wid  = tid >> 5;
    const int lane = tid & 31;
    const int wm   = wid >> 2;
    const int wn   = wid & 3;
    const int bm   = blockIdx.y * 128, bn = blockIdx.x * 128;

    const int lrow = tid >> 1;
    const int lcol = (tid & 1) * 16;
    const __half* gA = A + (size_t)(bm + lrow) * K + lcol;
    const __half* gB = B + (size_t)(bn + lrow) * K + lcol;
    const uint32_t ldst = (uint32_t)(lrow * MM_PAD + lcol) * 2;

    const int KT = K / MM_BK;
    const uint32_t a_off = (uint32_t)((wm * 64 + (lane & 15)) * MM_PAD + (lane >> 4) * 8) * 2;
    const uint32_t b_off = (uint32_t)((wn * 32 + (lane & 7)) * MM_PAD
                                      + ((lane >> 3) & 1) * 8) * 2;

    float acc[16][4];
    #pragma unroll
    for (int i = 0; i < 16; i++)
        #pragma unroll
        for (int j = 0; j < 4; j++) acc[i][j] = 0.0f;

    auto load_stage = [&](int st, int k0) {
        const uint32_t sa = sb + (uint32_t)st * MM_STAGE;
        CP_ASYNC16(sa + ldst,                 gA + k0);
        CP_ASYNC16(sa + ldst + 16,            gA + k0 + 8);
        CP_ASYNC16(sa + MM_AARR + ldst,       gB + k0);
        CP_ASYNC16(sa + MM_AARR + ldst + 16,  gB + k0 + 8);
    };

    load_stage(0, 0);     CP_COMMIT();
    load_stage(1, MM_BK); CP_COMMIT();

    int st = 0;
    for (int kt = 0; kt < KT; kt++) {
        CP_WAIT1();
        __syncthreads();
        const uint32_t stb = sb + (uint32_t)st * MM_STAGE;

        #pragma unroll
        for (int ks = 0; ks < 2; ks++) {
            const uint32_t kb = (uint32_t)(ks * 16) * 2;
            uint32_t ah[4][4], bh[4][2];
            #pragma unroll
            for (int mi = 0; mi < 4; mi++) {
                const uint32_t ao = stb + a_off + (uint32_t)(mi * 16 * MM_PAD) * 2 + kb;
                LDSM4(ah[mi][0], ah[mi][1], ah[mi][2], ah[mi][3], ao);
            }
            #pragma unroll
            for (int ni = 0; ni < 4; ni++) {
                const uint32_t bo = stb + MM_AARR + b_off
                                  + (uint32_t)(ni * 8 * MM_PAD) * 2 + kb;
                LDSM2(bh[ni][0], bh[ni][1], bo);
            }
            #pragma unroll
            for (int mi = 0; mi < 4; mi++)
                #pragma unroll
                for (int ni = 0; ni < 4; ni++)
                    MMA16816(acc[mi * 4 + ni], ah[mi], bh[ni]);
        }

        if (kt + 2 < KT) load_stage((st + 2) % 3, (kt + 2) * MM_BK);
        CP_COMMIT();
        st = (st + 1) % 3;
    }

    const int g  = lane >> 2;
    const int tc = (lane & 3) * 2;
    #pragma unroll
    for (int mi = 0; mi < 4; mi++) {
        #pragma unroll
        for (int ni = 0; ni < 4; ni++) {
            const float* a4 = acc[mi * 4 + ni];
            const int n = bn + wn * 32 + ni * 8 + tc;
            #pragma unroll
            for (int half_ = 0; half_ < 2; half_++) {
                const int m = bm + wm * 64 + mi * 16 + g + half_ * 8;
                float2 v = make_float2(a4[half_ * 2], a4[half_ * 2 + 1]);
                if (EPI == 1) {
                    v.x = softplusf(v.x + bias[n]);
                    v.y = softplusf(v.y + bias[n + 1]);
                    *(float2*)&C[(size_t)m * N + n] = v;
                } else if (EPI == 2) {
                    float2 s = *(const float2*)&add[(size_t)m * N + n];
                    v.x += s.x; v.y += s.y;
                    *(float2*)&C[(size_t)m * N + n] = v;
                } else { // EPI == 3
                    if (bn < DI) {
                        *(float2*)&C[(size_t)m * DI + n] = v;
                    } else {
                        float2 sv = make_float2(siluf(v.x), siluf(v.y));
                        *(float2*)&D2[(size_t)m * DI + (n - DI)] = sv;
                    }
                }
            }
        }
    }
}

// ============================ small kernels ================================

__global__ __launch_bounds__(256) void rmsnorm_kernel(
    const float* __restrict__ x, const float* __restrict__ w,
    __half* __restrict__ xh)
{
    int row = blockIdx.x, tid = threadIdx.x;
    const float* xr = x + (size_t)row * DM;
    float s = 0.0f;
    for (int i = tid; i < DM; i += 256) { float v = xr[i]; s += v * v; }
    #pragma unroll
    for (int o = 16; o > 0; o >>= 1) s += __shfl_down_sync(0xffffffffu, s, o);
    __shared__ float sm[8];
    if ((tid & 31) == 0) sm[tid >> 5] = s;
    __syncthreads();
    if (tid == 0) {
        float t = 0.0f;
        #pragma unroll
        for (int i = 0; i < 8; i++) t += sm[i];
        sm[0] = rsqrtf(t / (float)DM + 1e-6f);
    }
    __syncthreads();
    float inv = sm[0];
    for (int i = tid; i < DM; i += 256)
        xh[(size_t)row * DM + i] = __float2half(w[i] * xr[i] * inv);
}

__global__ __launch_bounds__(256) void cvt_f2h_kernel(
    const float* __restrict__ in, __half* __restrict__ out, int n4)
{
    int i = blockIdx.x * 256 + threadIdx.x;
    if (i >= n4) return;
    float4 v = *(const float4*)(in + (size_t)i * 4);
    __half2 p0 = __floats2half2_rn(v.x, v.y);
    __half2 p1 = __floats2half2_rn(v.z, v.w);
    *(uint2*)(out + (size_t)i * 4) = make_uint2(*(uint32_t*)&p0, *(uint32_t*)&p1);
}

__global__ __launch_bounds__(256) void conv_silu_kernel(
    const float* __restrict__ xi, const float* __restrict__ cw,
    const float* __restrict__ cb, float* __restrict__ xc,
    __half* __restrict__ xch)
{
    int idx = blockIdx.x * 256 + threadIdx.x;
    int c  = idx & (DI - 1);
    int bl = idx >> 11;
    int l  = bl & (SEQ - 1);
    int b  = bl >> 10;

    float acc = cb[c];
    #pragma unroll
    for (int k = 0; k < KCONV; k++) {
        int lp = l - (KCONV - 1) + k;
        if (lp >= 0)
            acc = fmaf(xi[((size_t)(b * SEQ + lp)) * DI + c], cw[c * KCONV + k], acc);
    }
    float v = siluf(acc);
    xc[(size_t)bl * DI + c]  = v;
    xch[(size_t)bl * DI + c] = __float2half(v);
}

#define GBM 128
#define GBK 16
#define SK_SLICES 16
#define SK_KLEN   (DI / SK_SLICES)

__global__ __launch_bounds__(256) void gemm_skinny64_splitk(
    const float* __restrict__ A, const float* __restrict__ B, float* __restrict__ C,
    int K)
{
    __shared__ float As[GBK][GBM + 4];
    __shared__ float Bs[GBK][64 + 4];

    const int tid = threadIdx.x;
    const int bm  = blockIdx.y * GBM;
    const int kb  = blockIdx.x * SK_KLEN;
    const int tx  = tid & 15;
    const int ty  = tid >> 4;
    const int lr  = tid >> 1;
    const int lc  = (tid & 1) * 8;
    const int lrB = tid >> 2;
    const int lcB = (tid & 3) * 4;

    const float* Aptr = A + (size_t)(bm + lr) * K + kb + lc;
    const float* Bptr = B + (size_t)lrB * K + kb + lcB;

    float acc[8][4];
    #pragma unroll
    for (int i = 0; i < 8; i++)
        #pragma unroll
        for (int j = 0; j < 4; j++) acc[i][j] = 0.0f;

    for (int k0 = 0; k0 < SK_KLEN; k0 += GBK) {
        float4 a0 = *(const float4*)(Aptr + k0);
        float4 a1 = *(const float4*)(Aptr + k0 + 4);
        float4 b0 = *(const float4*)(Bptr + k0);
        As[lc + 0][lr] = a0.x; As[lc + 1][lr] = a0.y;
        As[lc + 2][lr] = a0.z; As[lc + 3][lr] = a0.w;
        As[lc + 4][lr] = a1.x; As[lc + 5][lr] = a1.y;
        As[lc + 6][lr] = a1.z; As[lc + 7][lr] = a1.w;
        Bs[lcB + 0][lrB] = b0.x; Bs[lcB + 1][lrB] = b0.y;
        Bs[lcB + 2][lrB] = b0.z; Bs[lcB + 3][lrB] = b0.w;
        __syncthreads();
        #pragma unroll
        for (int k = 0; k < GBK; k++) {
            float4 av0 = *(const float4*)&As[k][ty * 8];
            float4 av1 = *(const float4*)&As[k][ty * 8 + 4];
            float4 bv0 = *(const float4*)&Bs[k][tx * 4];
            float av[8] = {av0.x, av0.y, av0.z, av0.w, av1.x, av1.y, av1.z, av1.w};
            float bv[4] = {bv0.x, bv0.y, bv0.z, bv0.w};
            #pragma unroll
            for (int i = 0; i < 8; i++)
                #pragma unroll
                for (int j = 0; j < 4; j++)
                    acc[i][j] = fmaf(av[i], bv[j], acc[i][j]);
        }
        __syncthreads();
    }
    #pragma unroll
    for (int i = 0; i < 8; i++) {
        int m = bm + ty * 8 + i;
        #pragma unroll
        for (int j = 0; j < 4; j++)
            atomicAdd(&C[(size_t)m * NST + tx * 4 + j], acc[i][j]);
    }
}

// ============================ scan =========================================
// Block = 16 warps = 16 channels (same batch), 512 threads, 256 blocks
// (single wave at 2 blocks/SM). Per 128-step chunk stage B (32 KB, shared by
// all 16 warps) + dt/xc/sres planes (8 KB each), double buffered (112 KB).
#define SCH    16
#define SCHUNK 128
#define NCH    (SEQ / SCHUNK)                 // 8
#define SC_BBUF  (SCHUNK * NST * 4)           // 32768
#define SC_PLANE (SCH * SCHUNK * 4)           // 8192
#define SC_STAGE (SC_BBUF + 3 * SC_PLANE)     // 57344
#define SC_SMEM  (2 * SC_STAGE)               // 114688

__global__ __launch_bounds__(512) void scan_kernel(
    const float* __restrict__ dtb, const float* __restrict__ xcb,
    const float* __restrict__ srb, const float* __restrict__ Bs,
    const float* __restrict__ A_log, const float* __restrict__ Dp,
    __half* __restrict__ zh)
{
    extern __shared__ char smem[];
    float* smf = (float*)smem;
    const uint32_t sb = smem_u32(smem);
    const int tid  = threadIdx.x;
    const int wid  = tid >> 5;
    const int lane = tid & 31;
    const int b    = blockIdx.x >> 7;             // 0..1 (128 blocks/batch)
    const int c0   = (blockIdx.x & 127) * SCH;
    const int c    = c0 + wid;

    const float LOG2E = 1.4426950408889634f;
    const float a0 = -expf(A_log[c * NST + 2 * lane + 0]) * LOG2E;
    const float a1 = -expf(A_log[c * NST + 2 * lane + 1]) * LOG2E;
    float h0 = 0.f, h1 = 0.f;
    const float Dc = Dp[c];

    const float* B_g  = Bs  + (size_t)(b * SEQ) * NST;
    const float* dt_g = dtb + (size_t)(b * SEQ) * DI;
    const float* xc_g = xcb + (size_t)(b * SEQ) * DI;
    const float* sr_g = srb + (size_t)(b * SEQ) * DI;
    __half* z_p = zh + (size_t)(b * SEQ) * DI + c;

    // chunk loader (512 threads):
    //  B: 2048 x 16B  (4 rounds),  planes: 512 x 16B each (1 round)
    auto load_chunk = [&](int st, int l0) {
        const uint32_t sB = sb + (uint32_t)st * SC_STAGE;
        #pragma unroll
        for (int r = 0; r < 4; r++) {
            const int i = tid + r * 512;           // 0..2047
            const int s = i >> 4, j = i & 15;
            CP_ASYNC16(sB + (uint32_t)i * 16, &B_g[(size_t)(l0 + s) * NST + j * 4]);
        }
        const int s = tid >> 2, hh = (tid & 3) * 4;  // 128 rows x 16 ch
        const size_t go = (size_t)(l0 + s) * DI + c0 + hh;
        CP_ASYNC16(sB + SC_BBUF                 + (uint32_t)tid * 16, &dt_g[go]);
        CP_ASYNC16(sB + SC_BBUF +     SC_PLANE  + (uint32_t)tid * 16, &xc_g[go]);
        CP_ASYNC16(sB + SC_BBUF + 2 * SC_PLANE  + (uint32_t)tid * 16, &sr_g[go]);
    };

    load_chunk(0, 0);      CP_COMMIT();
    load_chunk(1, SCHUNK); CP_COMMIT();

    for (int k = 0; k < NCH; k++) {
        CP_WAIT1();
        __syncthreads();
        const int st = k & 1;
        const int fB  = st * (SC_STAGE / 4);               // float index of B buf
        const int fDT = fB + SC_BBUF / 4;
        const int fXC = fDT + SC_PLANE / 4;
        const int fSR = fXC + SC_PLANE / 4;
        const int l0 = k * SCHUNK;

        #pragma unroll 4
        for (int s = 0; s < SCHUNK; s++) {
            float dtv = smf[fDT + s * SCH + wid];
            float xv  = smf[fXC + s * SCH + wid];
            float rv  = smf[fSR + s * SCH + wid];
            float2 Bv = *(const float2*)&smf[fB + s * NST + lane * 2];
            h0 = fmaf(ex2f(a0 * dtv), h0, Bv.x * xv);
            h1 = fmaf(ex2f(a1 * dtv), h1, Bv.y * xv);
            float y = h0 + h1;
            y += __shfl_down_sync(0xffffffffu, y, 16);
            y += __shfl_down_sync(0xffffffffu, y, 8);
            y += __shfl_down_sync(0xffffffffu, y, 4);
            y += __shfl_down_sync(0xffffffffu, y, 2);
            y += __shfl_down_sync(0xffffffffu, y, 1);
            if (lane == 0)
                z_p[(size_t)(l0 + s) * DI] = __float2half(fmaf(Dc, xv, y) * rv);
        }
        __syncthreads();

        if (k + 2 < NCH) load_chunk(st, (k + 2) * SCHUNK);
        CP_COMMIT();
    }
}

// ---------------------------------------------------------------------------
extern "C" void kernel_launch(void* const* d_in, const int* in_sizes, int n_in,
                              void* d_out, int out_size)
{
    const float* x        = (const float*)d_in[0];
    const float* norm_w   = (const float*)d_in[1];
    const float* in_proj  = (const float*)d_in[2];
    const float* conv_w   = (const float*)d_in[3];
    const float* conv_b   = (const float*)d_in[4];
    const float* x_proj   = (const float*)d_in[5];
    const float* dt_w     = (const float*)d_in[6];
    const float* dt_b     = (const float*)d_in[7];
    const float* A_log    = (const float*)d_in[8];
    const float* D_param  = (const float*)d_in[9];
    const float* out_proj = (const float*)d_in[10];
    float* out = (float*)d_out;

    float *xi, *sres, *dtb, *xc, *Bssm;
    __half *xnh, *w1h, *xch, *dwh, *zh, *owh;
    cudaGetSymbolAddress((void**)&xi,   g_xi);
    cudaGetSymbolAddress((void**)&sres, g_sres);
    cudaGetSymbolAddress((void**)&dtb,  g_dt);
    cudaGetSymbolAddress((void**)&xc,   g_xc);
    cudaGetSymbolAddress((void**)&Bssm, g_B);
    cudaGetSymbolAddress((void**)&xnh,  g_xn_h);
    cudaGetSymbolAddress((void**)&w1h,  g_w1_h);
    cudaGetSymbolAddress((void**)&xch,  g_xc_h);
    cudaGetSymbolAddress((void**)&dwh,  g_dw_h);
    cudaGetSymbolAddress((void**)&zh,   g_z_h);
    cudaGetSymbolAddress((void**)&owh,  g_ow_h);

    cudaFuncSetAttribute((const void*)mma_gemm<1>,
                         cudaFuncAttributeMaxDynamicSharedMemorySize, MM_SMEM);
    cudaFuncSetAttribute((const void*)mma_gemm<2>,
                         cudaFuncAttributeMaxDynamicSharedMemorySize, MM_SMEM);
    cudaFuncSetAttribute((const void*)mma_gemm<3>,
                         cudaFuncAttributeMaxDynamicSharedMemorySize, MM_SMEM);
    cudaFuncSetAttribute((const void*)scan_kernel,
                         cudaFuncAttributeMaxDynamicSharedMemorySize, SC_SMEM);

    cudaMemsetAsync(Bssm, 0, (size_t)ROWS * NST * sizeof(float), 0);

    cvt_f2h_kernel<<<(2*DI*DM/4 + 255)/256, 256>>>(in_proj, w1h, 2*DI*DM/4);
    rmsnorm_kernel<<<ROWS, 256>>>(x, norm_w, xnh);
    cvt_f2h_kernel<<<(DI*DI/4 + 255)/256, 256>>>(dt_w, dwh, DI*DI/4);

    // GEMM1 (EPI=3): n<DI -> xi; n>=DI -> silu -> sres  (coalesced)
    mma_gemm<3><<<dim3(2*DI/128, ROWS/128), 256, MM_SMEM>>>(
        xnh, w1h, xi, sres, ROWS, 2*DI, DM, nullptr, nullptr);

    conv_silu_kernel<<<ROWS * DI / 256, 256>>>(xi, conv_w, conv_b, xc, xch);

    // GEMM2 (EPI=1): dt = softplus(..) -> dtb  (coalesced)
    mma_gemm<1><<<dim3(DI/128, ROWS/128), 256, MM_SMEM>>>(
        xch, dwh, dtb, nullptr, ROWS, DI, DI, dt_b, nullptr);

    cvt_f2h_kernel<<<(DM*DI/4 + 255)/256, 256>>>(out_proj, owh, DM*DI/4);

    gemm_skinny64_splitk<<<dim3(SK_SLICES, ROWS/GBM), 256>>>(
        xc, x_proj + (size_t)NST * DI, Bssm, DI);

    // scan + gate -> z fp16 (256 blocks x 512 threads, single wave)
    scan_kernel<<<256, 512, SC_SMEM>>>(dtb, xc, sres, Bssm, A_log, D_param, zh);

    // GEMM3 (EPI=2): out = z @ out_proj^T + x
    mma_gemm<2><<<dim3(DM/128, ROWS/128), 256, MM_SMEM>>>(
        zh, owh, out, nullptr, ROWS, DM, DI, nullptr, x);
}